// round 5
// baseline (speedup 1.0000x reference)
#include <cuda_runtime.h>
#include <cuda_bf16.h>
#include <mma.h>
#include <math.h>
#include <stdint.h>

using namespace nvcuda;

#define Gn 512
#define Pn 128
#define Dn 256
#define En 1024
#define Hn 8
#define HDn 32
#define DFn 1024
#define Mn (Gn*Pn)

typedef unsigned long long u64t;

// ---------------- scratch ----------------
__device__ float g_h[(size_t)Mn*Dn];
__device__ float g_tmp[(size_t)Mn*Dn];
__device__ float g_qkv[(size_t)Mn*3*Dn];
__device__ __nv_bfloat16 g_as1[(size_t)Mn*2*Dn];
__device__ __nv_bfloat16 g_as2[(size_t)Mn*2*DFn];

#define W3_CONV   (Dn*3*Dn)                   // 196608
#define W3_FFN    (DFn*3*Dn)                  // 786432
#define W3_LAYER  (4*W3_CONV + 2*W3_FFN)
__device__ __nv_bfloat16 g_w3[2*W3_CONV + 2*W3_LAYER];

__device__ int   g_rp[Pn+1];
__device__ int   g_ci[En+Pn];
__device__ float g_wv[En+Pn];

// ---------------- helpers ----------------
__device__ __forceinline__ uint32_t smem_u32(const void* p) {
    uint32_t a;
    asm("{ .reg .u64 t; cvta.to.shared.u64 t, %1; cvt.u32.u64 %0, t; }" : "=r"(a) : "l"(p));
    return a;
}
__device__ __forceinline__ void cp_async16(uint32_t dst, const void* src) {
    asm volatile("cp.async.cg.shared.global [%0], [%1], 16;" :: "r"(dst), "l"(src) : "memory");
}
__device__ __forceinline__ void cp_commit() {
    asm volatile("cp.async.commit_group;" ::: "memory");
}
template<int N>
__device__ __forceinline__ void cp_wait() {
    asm volatile("cp.async.wait_group %0;" :: "n"(N) : "memory");
}
__device__ __forceinline__ u64t f2pack(float lo, float hi) {
    u64t r; asm("mov.b64 %0, {%1, %2};" : "=l"(r) : "f"(lo), "f"(hi)); return r;
}
__device__ __forceinline__ float2 f2unpack(u64t v) {
    float x, y; asm("mov.b64 {%0, %1}, %2;" : "=f"(x), "=f"(y) : "l"(v));
    return make_float2(x, y);
}
__device__ __forceinline__ u64t fma2(u64t a, u64t b, u64t c) {
    u64t d; asm("fma.rn.f32x2 %0, %1, %2, %3;" : "=l"(d) : "l"(a), "l"(b), "l"(c)); return d;
}
__device__ __forceinline__ void split2(float a, float b, __nv_bfloat162& hi, __nv_bfloat162& lo) {
    hi = __floats2bfloat162_rn(a, b);
    float2 f = __bfloat1622float2(hi);
    lo = __floats2bfloat162_rn(a - f.x, b - f.y);
}

// ---------------- fused graph setup (1 block) ----------------
__global__ void k_setup(const int* __restrict__ ei, int* rp, int* ci, float* wv) {
    __shared__ int   deg[Pn];
    __shared__ float dinv[Pn];
    __shared__ int   srp[Pn+1];
    __shared__ int   cur[Pn];
    int t = threadIdx.x;   // 128
    deg[t] = 1;
    __syncthreads();
    for (int e = t; e < En; e += Pn) atomicAdd(&deg[ei[En + e]], 1);
    __syncthreads();
    dinv[t] = rsqrtf((float)deg[t]);
    __syncthreads();
    if (t == 0) {
        int s = 0;
        for (int i = 0; i < Pn; i++) { srp[i] = s; cur[i] = s; s += deg[i]; }
        srp[Pn] = s;
    }
    __syncthreads();
    for (int e = t; e < En; e += Pn) {
        int s = ei[e], d = ei[En + e];
        int pos = atomicAdd(&cur[d], 1);
        ci[pos] = s; wv[pos] = dinv[s]*dinv[d];
    }
    {   // self loops
        int pos = atomicAdd(&cur[t], 1);
        ci[pos] = t; wv[pos] = dinv[t]*dinv[t];
    }
    rp[t] = srp[t];
    if (t == 0) rp[Pn] = srp[Pn];
}

// ---------------- fused weight pack: all 14 weights in one launch ----------
struct WD { const float* src; long long dst; int K; int N; };
struct WPack { WD d[14]; long long start[15]; };

__global__ void k_wprepAll(WPack p) {
    long long idx = (long long)blockIdx.x*256 + threadIdx.x;
    if (idx >= p.start[14]) return;
    int r = 0;
    #pragma unroll
    for (int i = 1; i < 14; i++) if (idx >= p.start[i]) r = i;
    long long local = idx - p.start[r];
    const WD d = p.d[r];
    int k = (int)(local / d.N), n = (int)(local - (long long)k*d.N);
    float a = d.src[local];
    __nv_bfloat16 h = __float2bfloat16_rn(a);
    __nv_bfloat16 l = __float2bfloat16_rn(a - __bfloat162float(h));
    __nv_bfloat16* O = g_w3 + d.dst + (size_t)n*3*d.K;
    O[k]         = h;
    O[d.K + k]   = l;
    O[2*d.K + k] = h;
}

// ---------------- input split: X[M,256] fp32 -> S[M,512] bf16 ---------------
__global__ void k_asplit(const float* __restrict__ X, __nv_bfloat16* __restrict__ S) {
    int idx = blockIdx.x*blockDim.x + threadIdx.x;
    int row = idx >> 6;
    int g   = (idx & 63) * 4;
    float4 v = reinterpret_cast<const float4*>(X)[idx];
    __nv_bfloat162 h01, l01, h23, l23;
    split2(v.x, v.y, h01, l01);
    split2(v.z, v.w, h23, l23);
    __nv_bfloat16* hp = S + (size_t)row*512 + g;
    *reinterpret_cast<__nv_bfloat162*>(hp)     = h01;
    *reinterpret_cast<__nv_bfloat162*>(hp + 2) = h23;
    *reinterpret_cast<__nv_bfloat162*>(hp + 256)     = l01;
    *reinterpret_cast<__nv_bfloat162*>(hp + 256 + 2) = l23;
}

// ---------------- WMMA GEMM, BM=128 BN=256 BK=32, 4-stage cp.async ---------
// A2: [M][2K] bf16 hi|lo ; B3: [Ntot][3K] bf16 hi|lo|hi (k-contiguous rows)
// BMODE: 0 none, 1 single bias (global col), 2 per-n-block bias (QKV)
#define ASTR 40
#define STAGE_B 30720            // 10240 (A) + 20480 (B)
#define GEMM_SMEM (4*STAGE_B)    // 122880; epilogue stage 69632 overlaps

template<int BMODE, bool RELU, bool WF32, bool WSPLIT>
__global__ void __launch_bounds__(256)
gemm_tc(const __nv_bfloat16* __restrict__ A2, long long lda,
        const __nv_bfloat16* __restrict__ B3, long long ldb,
        const float* __restrict__ b0, const float* __restrict__ b1p,
        const float* __restrict__ b2p,
        float* __restrict__ C, __nv_bfloat16* __restrict__ Csp,
        int K, int Ntot)
{
    extern __shared__ __align__(128) char dsm[];
    const int tid = threadIdx.x;
    const int wid = tid >> 5;
    const int wm = wid & 1;       // 0..1
    const int wn = wid >> 1;      // 0..3
    const int m0 = blockIdx.y * 128;
    const int n0 = blockIdx.x * 256;
    uint32_t sbase = smem_u32(dsm);

    const int nc = K >> 5;
    const int NC = 3*nc;

    wmma::fragment<wmma::accumulator, 16,16,16, float> acc[4][4];
    #pragma unroll
    for (int i = 0; i < 4; i++)
        #pragma unroll
        for (int j = 0; j < 4; j++) wmma::fill_fragment(acc[i][j], 0.f);

    auto load_chunk = [&](int c, int stage) {
        int acol = (c < 2*nc) ? (((c < nc) ? c : c - nc) << 5) : (K + ((c - 2*nc) << 5));
        int bcol = c << 5;
        uint32_t da = sbase + stage*STAGE_B;
        uint32_t db = da + 10240;
        #pragma unroll
        for (int r = 0; r < 2; r++) {
            int id = tid + r*256;
            int row = id >> 2, seg = id & 3;
            cp_async16(da + row*80 + seg*16,
                       A2 + (size_t)(m0+row)*lda + acol + seg*8);
        }
        #pragma unroll
        for (int r = 0; r < 4; r++) {
            int id = tid + r*256;
            int row = id >> 2, seg = id & 3;
            cp_async16(db + row*80 + seg*16,
                       B3 + (size_t)(n0+row)*ldb + bcol + seg*8);
        }
        cp_commit();
    };

    load_chunk(0, 0);
    load_chunk(1, 1);
    load_chunk(2, 2);

    for (int c = 0; c < NC; c++) {
        const int stage = c & 3;
        if (c <= NC-3)      cp_wait<2>();
        else if (c == NC-2) cp_wait<1>();
        else                cp_wait<0>();
        __syncthreads();
        if (c + 3 < NC) load_chunk(c+3, (c+3) & 3);

        const __nv_bfloat16* As = reinterpret_cast<const __nv_bfloat16*>(dsm + stage*STAGE_B);
        const __nv_bfloat16* Bs = As + 5120;
        #pragma unroll
        for (int ks = 0; ks < 2; ks++) {
            wmma::fragment<wmma::matrix_a, 16,16,16, __nv_bfloat16, wmma::row_major> af[4];
            wmma::fragment<wmma::matrix_b, 16,16,16, __nv_bfloat16, wmma::col_major> bfr[4];
            #pragma unroll
            for (int mt = 0; mt < 4; mt++)
                wmma::load_matrix_sync(af[mt], As + (wm*64 + mt*16)*ASTR + ks*16, ASTR);
            #pragma unroll
            for (int nt = 0; nt < 4; nt++)
                wmma::load_matrix_sync(bfr[nt], Bs + (wn*64 + nt*16)*ASTR + ks*16, ASTR);
            #pragma unroll
            for (int mt = 0; mt < 4; mt++)
                #pragma unroll
                for (int nt = 0; nt < 4; nt++)
                    wmma::mma_sync(acc[mt][nt], af[mt], bfr[nt], acc[mt][nt]);
        }
    }

    // bias pointer
    const float* bp = nullptr;
    int bbase = 0;
    if (BMODE == 1) { bp = b0; bbase = n0; }
    if (BMODE == 2) { bp = (blockIdx.x == 0) ? b0 : ((blockIdx.x == 1) ? b1p : b2p); bbase = 0; }

    // epilogue in two 128-col halves, smem-staged
    float* stg = reinterpret_cast<float*>(dsm);
    #pragma unroll
    for (int hh = 0; hh < 2; hh++) {
        __syncthreads();
        if ((wn >> 1) == hh) {
            #pragma unroll
            for (int mt = 0; mt < 4; mt++)
                #pragma unroll
                for (int nt = 0; nt < 4; nt++)
                    wmma::store_matrix_sync(stg + (wm*64 + mt*16)*136 + (wn & 1)*64 + nt*16,
                                            acc[mt][nt], 136, wmma::mem_row_major);
        }
        __syncthreads();
        int row = tid >> 1;
        int cb  = (tid & 1) * 64;
        const float* sr = stg + row*136 + cb;
        int gcol = n0 + hh*128 + cb;
        size_t crow  = (size_t)(m0+row)*Ntot + gcol;
        size_t shrow = (size_t)(m0+row)*(2*(size_t)Ntot) + gcol;
        #pragma unroll
        for (int j = 0; j < 64; j += 4) {
            float4 v = *reinterpret_cast<const float4*>(sr + j);
            if (BMODE) {
                float4 b = *reinterpret_cast<const float4*>(bp + bbase + hh*128 + cb + j);
                v.x += b.x; v.y += b.y; v.z += b.z; v.w += b.w;
            }
            if (RELU) {
                v.x = fmaxf(v.x, 0.f); v.y = fmaxf(v.y, 0.f);
                v.z = fmaxf(v.z, 0.f); v.w = fmaxf(v.w, 0.f);
            }
            if (WF32) *reinterpret_cast<float4*>(C + crow + j) = v;
            if (WSPLIT) {
                __nv_bfloat162 h01, l01, h23, l23;
                split2(v.x, v.y, h01, l01);
                split2(v.z, v.w, h23, l23);
                __nv_bfloat16* hp = Csp + shrow + j;
                *reinterpret_cast<__nv_bfloat162*>(hp)     = h01;
                *reinterpret_cast<__nv_bfloat162*>(hp + 2) = h23;
                *reinterpret_cast<__nv_bfloat162*>(hp + Ntot)     = l01;
                *reinterpret_cast<__nv_bfloat162*>(hp + Ntot + 2) = l23;
            }
        }
    }
}

// ---------------- sparse GCN aggregation (+bias +relu) ----------------------
template<bool WF32>
__global__ void __launch_bounds__(256)
agg_csr(const float* __restrict__ xw, const int* __restrict__ rp,
        const int* __restrict__ ci, const float* __restrict__ wv,
        const float* __restrict__ bias, float* __restrict__ outf,
        __nv_bfloat16* __restrict__ sp)
{
    int warp = blockIdx.x*8 + (threadIdx.x >> 5);
    int lane = threadIdx.x & 31;
    int p = warp & 127;
    size_t gbase = (size_t)(warp & ~127) * Dn;

    float4 a0 = make_float4(0.f,0.f,0.f,0.f);
    float4 a1 = make_float4(0.f,0.f,0.f,0.f);
    int s0 = rp[p], s1 = rp[p+1];
    for (int e = s0; e < s1; e++) {
        int src = ci[e]; float w = wv[e];
        const float4* rowp = reinterpret_cast<const float4*>(xw + gbase + (size_t)src*Dn);
        float4 x0 = rowp[lane];
        float4 x1 = rowp[lane+32];
        a0.x = fmaf(w, x0.x, a0.x); a0.y = fmaf(w, x0.y, a0.y);
        a0.z = fmaf(w, x0.z, a0.z); a0.w = fmaf(w, x0.w, a0.w);
        a1.x = fmaf(w, x1.x, a1.x); a1.y = fmaf(w, x1.y, a1.y);
        a1.z = fmaf(w, x1.z, a1.z); a1.w = fmaf(w, x1.w, a1.w);
    }
    int c0 = lane*4;
    float4 b0 = *reinterpret_cast<const float4*>(bias + c0);
    float4 b1 = *reinterpret_cast<const float4*>(bias + c0 + 128);
    a0.x = fmaxf(a0.x + b0.x, 0.f); a0.y = fmaxf(a0.y + b0.y, 0.f);
    a0.z = fmaxf(a0.z + b0.z, 0.f); a0.w = fmaxf(a0.w + b0.w, 0.f);
    a1.x = fmaxf(a1.x + b1.x, 0.f); a1.y = fmaxf(a1.y + b1.y, 0.f);
    a1.z = fmaxf(a1.z + b1.z, 0.f); a1.w = fmaxf(a1.w + b1.w, 0.f);

    if (WF32) {
        float* dst = outf + (size_t)warp*Dn;
        *reinterpret_cast<float4*>(dst + c0)       = a0;
        *reinterpret_cast<float4*>(dst + c0 + 128) = a1;
    }
    __nv_bfloat16* sprow = sp + (size_t)warp*512;
    __nv_bfloat162 h01, l01, h23, l23;
    split2(a0.x, a0.y, h01, l01); split2(a0.z, a0.w, h23, l23);
    *reinterpret_cast<__nv_bfloat162*>(sprow + c0)     = h01;
    *reinterpret_cast<__nv_bfloat162*>(sprow + c0 + 2) = h23;
    *reinterpret_cast<__nv_bfloat162*>(sprow + 256 + c0)     = l01;
    *reinterpret_cast<__nv_bfloat162*>(sprow + 256 + c0 + 2) = l23;
    split2(a1.x, a1.y, h01, l01); split2(a1.z, a1.w, h23, l23);
    *reinterpret_cast<__nv_bfloat162*>(sprow + c0 + 128)     = h01;
    *reinterpret_cast<__nv_bfloat162*>(sprow + c0 + 130)     = h23;
    *reinterpret_cast<__nv_bfloat162*>(sprow + 256 + c0 + 128) = l01;
    *reinterpret_cast<__nv_bfloat162*>(sprow + 256 + c0 + 130) = l23;
}

// ---------------- attention: f32x2-packed, one CTA per (head, graph) -------
__global__ void __launch_bounds__(128)
attn_kernel(const float* __restrict__ qkv, __nv_bfloat16* __restrict__ sp)
{
    int head = blockIdx.x;
    int g    = blockIdx.y;
    int tid  = threadIdx.x;

    __shared__ u64t Ks[Pn][HDn/2];
    __shared__ u64t Vs[Pn][HDn/2];

    size_t base = ((size_t)g*Pn + tid)*768 + head*HDn;
    u64t qr[HDn/2];
    #pragma unroll
    for (int j = 0; j < HDn/4; j++) {
        float4 qv = reinterpret_cast<const float4*>(qkv + base)[j];
        float4 kv = reinterpret_cast<const float4*>(qkv + base + 256)[j];
        float4 vv = reinterpret_cast<const float4*>(qkv + base + 512)[j];
        qr[2*j]   = f2pack(qv.x, qv.y);
        qr[2*j+1] = f2pack(qv.z, qv.w);
        Ks[tid][2*j]   = f2pack(kv.x, kv.y);
        Ks[tid][2*j+1] = f2pack(kv.z, kv.w);
        Vs[tid][2*j]   = f2pack(vv.x, vv.y);
        Vs[tid][2*j+1] = f2pack(vv.z, vv.w);
    }
    __syncthreads();

    const float scale = 0.17677669529663687f;   // 1/sqrt(32)
    float l = 0.f;
    u64t acc[HDn/2];
    #pragma unroll
    for (int d = 0; d < HDn/2; d++) acc[d] = 0ull;

    for (int j = 0; j < Pn; j++) {
        u64t s2 = 0ull;
        #pragma unroll
        for (int d = 0; d < HDn/2; d++) s2 = fma2(qr[d], Ks[j][d], s2);
        float2 sv = f2unpack(s2);
        float e = __expf((sv.x + sv.y)*scale);
        l += e;
        u64t ee = f2pack(e, e);
        #pragma unroll
        for (int d = 0; d < HDn/2; d++) acc[d] = fma2(ee, Vs[j][d], acc[d]);
    }
    float inv = 1.f / l;
    __nv_bfloat16* sprow = sp + ((size_t)g*Pn + tid)*512 + head*HDn;
    #pragma unroll
    for (int d = 0; d < HDn/2; d += 2) {
        float2 p0 = f2unpack(acc[d]);
        float2 p1 = f2unpack(acc[d+1]);
        __nv_bfloat162 h01, l01, h23, l23;
        split2(p0.x*inv, p0.y*inv, h01, l01);
        split2(p1.x*inv, p1.y*inv, h23, l23);
        *reinterpret_cast<__nv_bfloat162*>(sprow + 2*d)     = h01;
        *reinterpret_cast<__nv_bfloat162*>(sprow + 2*d + 2) = h23;
        *reinterpret_cast<__nv_bfloat162*>(sprow + 256 + 2*d)     = l01;
        *reinterpret_cast<__nv_bfloat162*>(sprow + 256 + 2*d + 2) = l23;
    }
}

// ---------------- LayerNorm(x + t)*g + b --------------------------------
template<bool WSPLIT>
__global__ void __launch_bounds__(Dn)
ln_kernel(const float* __restrict__ x, const float* __restrict__ t,
          const float* __restrict__ gam, const float* __restrict__ bet,
          float* __restrict__ out, __nv_bfloat16* __restrict__ sp)
{
    int row = blockIdx.x;
    int f   = threadIdx.x;
    size_t idx = (size_t)row*Dn + f;
    float v = x[idx] + t[idx];

    __shared__ float sh[8];
    int lane = f & 31, w = f >> 5;

    float s = v;
    #pragma unroll
    for (int off = 16; off > 0; off >>= 1) s += __shfl_xor_sync(0xffffffffu, s, off);
    if (lane == 0) sh[w] = s;
    __syncthreads();
    float mean = 0.f;
    #pragma unroll
    for (int i = 0; i < 8; i++) mean += sh[i];
    mean *= (1.f/Dn);

    float d  = v - mean;
    float s2 = d*d;
    #pragma unroll
    for (int off = 16; off > 0; off >>= 1) s2 += __shfl_xor_sync(0xffffffffu, s2, off);
    __syncthreads();
    if (lane == 0) sh[w] = s2;
    __syncthreads();
    float var = 0.f;
    #pragma unroll
    for (int i = 0; i < 8; i++) var += sh[i];
    var *= (1.f/Dn);

    float r = rsqrtf(var + 1e-5f);
    float o = d*r*gam[f] + bet[f];
    out[idx] = o;
    if (WSPLIT) {
        __nv_bfloat16 hb = __float2bfloat16_rn(o);
        __nv_bfloat16 lb = __float2bfloat16_rn(o - __bfloat162float(hb));
        sp[(size_t)row*512 + f]       = hb;
        sp[(size_t)row*512 + 256 + f] = lb;
    }
}

// ---------------------------------------------------------------------------
extern "C" void kernel_launch(void* const* d_in, const int* in_sizes, int n_in,
                              void* d_out, int out_size)
{
    const float* x    = (const float*)d_in[0];
    const int*   ei   = (const int*)  d_in[1];
    const float* c1W  = (const float*)d_in[6];
    const float* c1b  = (const float*)d_in[7];
    const float* c2W  = (const float*)d_in[8];
    const float* c2b  = (const float*)d_in[9];
    const float* WqA  = (const float*)d_in[10];
    const float* bqA  = (const float*)d_in[11];
    const float* WkA  = (const float*)d_in[12];
    const float* bkA  = (const float*)d_in[13];
    const float* WvA  = (const float*)d_in[14];
    const float* bvA  = (const float*)d_in[15];
    const float* WoA  = (const float*)d_in[16];
    const float* boA  = (const float*)d_in[17];
    const float* W1A  = (const float*)d_in[18];
    const float* b1A  = (const float*)d_in[19];
    const float* W2A  = (const float*)d_in[20];
    const float* b2A  = (const float*)d_in[21];
    const float* l1gA = (const float*)d_in[22];
    const float* l1bA = (const float*)d_in[23];
    const float* l2gA = (const float*)d_in[24];
    const float* l2bA = (const float*)d_in[25];
    float* out = (float*)d_out;

    float *h, *tmp, *qkv, *wv;
    __nv_bfloat16 *as1, *as2, *w3;
    int *rp, *ci;
    cudaGetSymbolAddress((void**)&h,    g_h);
    cudaGetSymbolAddress((void**)&tmp,  g_tmp);
    cudaGetSymbolAddress((void**)&qkv,  g_qkv);
    cudaGetSymbolAddress((void**)&as1,  g_as1);
    cudaGetSymbolAddress((void**)&as2,  g_as2);
    cudaGetSymbolAddress((void**)&w3,   g_w3);
    cudaGetSymbolAddress((void**)&rp,   g_rp);
    cudaGetSymbolAddress((void**)&ci,   g_ci);
    cudaGetSymbolAddress((void**)&wv,   g_wv);

    cudaFuncSetAttribute(gemm_tc<0,false,true ,false>, cudaFuncAttributeMaxDynamicSharedMemorySize, GEMM_SMEM);
    cudaFuncSetAttribute(gemm_tc<2,false,true ,false>, cudaFuncAttributeMaxDynamicSharedMemorySize, GEMM_SMEM);
    cudaFuncSetAttribute(gemm_tc<1,false,true ,false>, cudaFuncAttributeMaxDynamicSharedMemorySize, GEMM_SMEM);
    cudaFuncSetAttribute(gemm_tc<1,true ,false,true >, cudaFuncAttributeMaxDynamicSharedMemorySize, GEMM_SMEM);

    // ---- launch 0: graph setup ----
    k_setup<<<1, Pn>>>(ei, rp, ci, wv);

    // ---- launch 1: all weight packs ----
    const long long oC1 = 0, oC2 = W3_CONV;
    const long long oL  = 2*W3_CONV;
    WPack wp;
    {
        int i = 0;
        long long s = 0;
        auto add = [&](const float* src, long long dst, int K, int N) {
            wp.d[i] = {src, dst, K, N};
            wp.start[i] = s;
            s += (long long)K*N;
            i++;
        };
        add(c1W, oC1, Dn, Dn);
        add(c2W, oC2, Dn, Dn);
        for (int l = 0; l < 2; l++) {
            long long b = oL + (long long)l*W3_LAYER;
            add(WqA + (size_t)l*65536,  b,             Dn, Dn);
            add(WkA + (size_t)l*65536,  b + W3_CONV,   Dn, Dn);
            add(WvA + (size_t)l*65536,  b + 2*W3_CONV, Dn, Dn);
            add(WoA + (size_t)l*65536,  b + 3*W3_CONV, Dn, Dn);
            add(W1A + (size_t)l*262144, b + 4*W3_CONV, Dn, DFn);
            add(W2A + (size_t)l*262144, b + 4*W3_CONV + W3_FFN, DFn, Dn);
        }
        wp.start[14] = s;
    }
    k_wprepAll<<<(int)((wp.start[14] + 255)/256), 256>>>(wp);

    // ---- launch 2: input split ----
    k_asplit<<<(Mn*64)/256, 256>>>(x, as1);

    dim3 gD(1, Mn/128);
    dim3 gQKV(3, Mn/128);
    dim3 gF1(4, Mn/128);

    // ---- launch 3 (profiled): GCN conv1 GEMM ----
    gemm_tc<0,false,true,false><<<gD, 256, GEMM_SMEM>>>(as1, 512, w3 + oC1, 768, nullptr, nullptr, nullptr, tmp, nullptr, Dn, Dn);
    agg_csr<false><<<Mn/8, 256>>>(tmp, rp, ci, wv, c1b, nullptr, as1);
    gemm_tc<0,false,true,false><<<gD, 256, GEMM_SMEM>>>(as1, 512, w3 + oC2, 768, nullptr, nullptr, nullptr, tmp, nullptr, Dn, Dn);
    agg_csr<true ><<<Mn/8, 256>>>(tmp, rp, ci, wv, c2b, h, as1);

    for (int l = 0; l < 2; l++) {
        long long b = oL + (long long)l*W3_LAYER;
        const float* bq = bqA + (size_t)l*Dn;
        const float* bk = bkA + (size_t)l*Dn;
        const float* bv = bvA + (size_t)l*Dn;
        const float* bo = boA + (size_t)l*Dn;
        const float* b1 = b1A + (size_t)l*DFn;
        const float* b2 = b2A + (size_t)l*Dn;
        const float* l1g = l1gA + (size_t)l*Dn; const float* l1b = l1bA + (size_t)l*Dn;
        const float* l2g = l2gA + (size_t)l*Dn; const float* l2b = l2bA + (size_t)l*Dn;

        // fused QKV: B rows 0..767 = Wq|Wk|Wv packs (contiguous)
        gemm_tc<2,false,true,false><<<gQKV, 256, GEMM_SMEM>>>(as1, 512, w3 + b, 768, bq, bk, bv, qkv, nullptr, Dn, 768);

        attn_kernel<<<dim3(Hn, Gn), 128>>>(qkv, as1);

        gemm_tc<1,false,true,false><<<gD, 256, GEMM_SMEM>>>(as1, 512, w3 + b + 3*W3_CONV, 768, bo, nullptr, nullptr, tmp, nullptr, Dn, Dn);
        ln_kernel<true><<<Mn, Dn>>>(h, tmp, l1g, l1b, h, as1);

        gemm_tc<1,true,false,true><<<gF1, 256, GEMM_SMEM>>>(as1, 512, w3 + b + 4*W3_CONV, 768, b1, nullptr, nullptr, nullptr, as2, Dn, DFn);
        gemm_tc<1,false,true,false><<<gD, 256, GEMM_SMEM>>>(as2, 2048, w3 + b + 4*W3_CONV + W3_FFN, 3072, b2, nullptr, nullptr, tmp, nullptr, DFn, Dn);

        if (l == 0) ln_kernel<true ><<<Mn, Dn>>>(h, tmp, l2g, l2b, h, as1);
        else        ln_kernel<false><<<Mn, Dn>>>(h, tmp, l2g, l2b, out, nullptr);
    }
}

// round 6
// speedup vs baseline: 1.1107x; 1.1107x over previous
#include <cuda_runtime.h>
#include <cuda_bf16.h>
#include <mma.h>
#include <math.h>
#include <stdint.h>

using namespace nvcuda;

#define Gn 512
#define Pn 128
#define Dn 256
#define En 1024
#define Hn 8
#define HDn 32
#define DFn 1024
#define Mn (Gn*Pn)

typedef unsigned long long u64t;

// ---------------- scratch ----------------
__device__ float g_h[(size_t)Mn*Dn];
__device__ float g_tmp[(size_t)Mn*Dn];
__device__ float g_qkv[(size_t)Mn*3*Dn];
__device__ __nv_bfloat16 g_as1[(size_t)Mn*2*Dn];
__device__ __nv_bfloat16 g_as2[(size_t)Mn*2*DFn];

#define W3_CONV   (Dn*3*Dn)                   // 196608
#define W3_FFN    (DFn*3*Dn)                  // 786432
#define W3_LAYER  (4*W3_CONV + 2*W3_FFN)
__device__ __nv_bfloat16 g_w3[2*W3_CONV + 2*W3_LAYER];

__device__ int   g_rp[Pn+1];
__device__ int   g_ci[En+Pn];
__device__ float g_wv[En+Pn];

// ---------------- helpers ----------------
__device__ __forceinline__ uint32_t smem_u32(const void* p) {
    uint32_t a;
    asm("{ .reg .u64 t; cvta.to.shared.u64 t, %1; cvt.u32.u64 %0, t; }" : "=r"(a) : "l"(p));
    return a;
}
__device__ __forceinline__ void cp_async16(uint32_t dst, const void* src) {
    asm volatile("cp.async.cg.shared.global [%0], [%1], 16;" :: "r"(dst), "l"(src) : "memory");
}
__device__ __forceinline__ void cp_commit() {
    asm volatile("cp.async.commit_group;" ::: "memory");
}
template<int N>
__device__ __forceinline__ void cp_wait() {
    asm volatile("cp.async.wait_group %0;" :: "n"(N) : "memory");
}
__device__ __forceinline__ u64t f2pack(float lo, float hi) {
    u64t r; asm("mov.b64 %0, {%1, %2};" : "=l"(r) : "f"(lo), "f"(hi)); return r;
}
__device__ __forceinline__ float2 f2unpack(u64t v) {
    float x, y; asm("mov.b64 {%0, %1}, %2;" : "=f"(x), "=f"(y) : "l"(v));
    return make_float2(x, y);
}
__device__ __forceinline__ u64t fma2(u64t a, u64t b, u64t c) {
    u64t d; asm("fma.rn.f32x2 %0, %1, %2, %3;" : "=l"(d) : "l"(a), "l"(b), "l"(c)); return d;
}
__device__ __forceinline__ void split2(float a, float b, __nv_bfloat162& hi, __nv_bfloat162& lo) {
    hi = __floats2bfloat162_rn(a, b);
    float2 f = __bfloat1622float2(hi);
    lo = __floats2bfloat162_rn(a - f.x, b - f.y);
}

// ---------------- fused graph setup (1 block) ----------------
__global__ void k_setup(const int* __restrict__ ei, int* rp, int* ci, float* wv) {
    __shared__ int   deg[Pn];
    __shared__ float dinv[Pn];
    __shared__ int   srp[Pn+1];
    __shared__ int   cur[Pn];
    int t = threadIdx.x;   // 128
    deg[t] = 1;
    __syncthreads();
    for (int e = t; e < En; e += Pn) atomicAdd(&deg[ei[En + e]], 1);
    __syncthreads();
    dinv[t] = rsqrtf((float)deg[t]);
    __syncthreads();
    if (t == 0) {
        int s = 0;
        for (int i = 0; i < Pn; i++) { srp[i] = s; cur[i] = s; s += deg[i]; }
        srp[Pn] = s;
    }
    __syncthreads();
    for (int e = t; e < En; e += Pn) {
        int s = ei[e], d = ei[En + e];
        int pos = atomicAdd(&cur[d], 1);
        ci[pos] = s; wv[pos] = dinv[s]*dinv[d];
    }
    {   // self loops
        int pos = atomicAdd(&cur[t], 1);
        ci[pos] = t; wv[pos] = dinv[t]*dinv[t];
    }
    rp[t] = srp[t];
    if (t == 0) rp[Pn] = srp[Pn];
}

// ---------------- fused weight pack: all 14 weights in one launch ----------
struct WD { const float* src; long long dst; int K; int N; };
struct WPack { WD d[14]; long long start[15]; };

__global__ void k_wprepAll(WPack p) {
    long long idx = (long long)blockIdx.x*256 + threadIdx.x;
    if (idx >= p.start[14]) return;
    int r = 0;
    #pragma unroll
    for (int i = 1; i < 14; i++) if (idx >= p.start[i]) r = i;
    long long local = idx - p.start[r];
    const WD d = p.d[r];
    int k = (int)(local / d.N), n = (int)(local - (long long)k*d.N);
    float a = d.src[local];
    __nv_bfloat16 h = __float2bfloat16_rn(a);
    __nv_bfloat16 l = __float2bfloat16_rn(a - __bfloat162float(h));
    __nv_bfloat16* O = g_w3 + d.dst + (size_t)n*3*d.K;
    O[k]         = h;
    O[d.K + k]   = l;
    O[2*d.K + k] = h;
}

// ---------------- input split: X[M,256] fp32 -> S[M,512] bf16 ---------------
__global__ void k_asplit(const float* __restrict__ X, __nv_bfloat16* __restrict__ S) {
    int idx = blockIdx.x*blockDim.x + threadIdx.x;
    int row = idx >> 6;
    int g   = (idx & 63) * 4;
    float4 v = reinterpret_cast<const float4*>(X)[idx];
    __nv_bfloat162 h01, l01, h23, l23;
    split2(v.x, v.y, h01, l01);
    split2(v.z, v.w, h23, l23);
    __nv_bfloat16* hp = S + (size_t)row*512 + g;
    *reinterpret_cast<__nv_bfloat162*>(hp)     = h01;
    *reinterpret_cast<__nv_bfloat162*>(hp + 2) = h23;
    *reinterpret_cast<__nv_bfloat162*>(hp + 256)     = l01;
    *reinterpret_cast<__nv_bfloat162*>(hp + 256 + 2) = l23;
}

// ---------------- WMMA GEMM, BM=128 BN=128 BK=32, 3-stage, 2 CTAs/SM -------
// A2: [M][2K] bf16 hi|lo ; B3: [Ntot][3K] bf16 hi|lo|hi (k-contiguous rows)
// BMODE: 0 none, 1 single bias (global col), 2 per-128col bias (QKV)
#define ASTR 40
#define STAGE_B 20480            // 10240 (A) + 10240 (B)
#define GEMM_SMEM 69632          // epilogue 128*136*4 dominates 3*20480=61440

template<int BMODE, bool RELU, bool WF32, bool WSPLIT>
__global__ void __launch_bounds__(256, 2)
gemm_tc(const __nv_bfloat16* __restrict__ A2, long long lda,
        const __nv_bfloat16* __restrict__ B3, long long ldb,
        const float* __restrict__ b0, const float* __restrict__ b1p,
        const float* __restrict__ b2p,
        float* __restrict__ C, __nv_bfloat16* __restrict__ Csp,
        int K, int Ntot)
{
    extern __shared__ __align__(128) char dsm[];
    const int tid = threadIdx.x;
    const int wid = tid >> 5;
    const int wm = wid & 1;       // 0..1  (64-row slice)
    const int wn = wid >> 1;      // 0..3  (32-col slice)
    const int m0 = blockIdx.y * 128;
    const int n0 = blockIdx.x * 128;
    uint32_t sbase = smem_u32(dsm);

    const int nc = K >> 5;
    const int NC = 3*nc;

    wmma::fragment<wmma::accumulator, 16,16,16, float> acc[4][2];
    #pragma unroll
    for (int i = 0; i < 4; i++)
        #pragma unroll
        for (int j = 0; j < 2; j++) wmma::fill_fragment(acc[i][j], 0.f);

    auto load_chunk = [&](int c, int stage) {
        int acol = (c < 2*nc) ? (((c < nc) ? c : c - nc) << 5) : (K + ((c - 2*nc) << 5));
        int bcol = c << 5;
        uint32_t da = sbase + stage*STAGE_B;
        uint32_t db = da + 10240;
        #pragma unroll
        for (int r = 0; r < 2; r++) {
            int id = tid + r*256;
            int row = id >> 2, seg = id & 3;
            cp_async16(da + row*80 + seg*16,
                       A2 + (size_t)(m0+row)*lda + acol + seg*8);
            cp_async16(db + row*80 + seg*16,
                       B3 + (size_t)(n0+row)*ldb + bcol + seg*8);
        }
        cp_commit();
    };

    load_chunk(0, 0);
    load_chunk(1, 1);

    for (int c = 0; c < NC; c++) {
        const int stage = c - (c/3)*3;   // c % 3
        if (c + 1 < NC) cp_wait<1>();
        else            cp_wait<0>();
        __syncthreads();
        if (c + 2 < NC) {
            int s2 = (c+2) - ((c+2)/3)*3;
            load_chunk(c+2, s2);
        }

        const __nv_bfloat16* As = reinterpret_cast<const __nv_bfloat16*>(dsm + stage*STAGE_B);
        const __nv_bfloat16* Bs = As + 5120;
        #pragma unroll
        for (int ks = 0; ks < 2; ks++) {
            wmma::fragment<wmma::matrix_a, 16,16,16, __nv_bfloat16, wmma::row_major> af[4];
            wmma::fragment<wmma::matrix_b, 16,16,16, __nv_bfloat16, wmma::col_major> bfr[2];
            #pragma unroll
            for (int mt = 0; mt < 4; mt++)
                wmma::load_matrix_sync(af[mt], As + (wm*64 + mt*16)*ASTR + ks*16, ASTR);
            #pragma unroll
            for (int nt = 0; nt < 2; nt++)
                wmma::load_matrix_sync(bfr[nt], Bs + (wn*32 + nt*16)*ASTR + ks*16, ASTR);
            #pragma unroll
            for (int mt = 0; mt < 4; mt++)
                #pragma unroll
                for (int nt = 0; nt < 2; nt++)
                    wmma::mma_sync(acc[mt][nt], af[mt], bfr[nt], acc[mt][nt]);
        }
        __syncthreads();
    }

    // bias pointer
    const float* bp = nullptr;
    int bbase = 0;
    if (BMODE == 1) { bp = b0; bbase = n0; }
    if (BMODE == 2) {
        int sel = blockIdx.x >> 1;
        bp = (sel == 0) ? b0 : ((sel == 1) ? b1p : b2p);
        bbase = (blockIdx.x & 1) * 128;
    }

    // epilogue: smem-staged, one pass
    float* stg = reinterpret_cast<float*>(dsm);
    #pragma unroll
    for (int mt = 0; mt < 4; mt++)
        #pragma unroll
        for (int nt = 0; nt < 2; nt++)
            wmma::store_matrix_sync(stg + (wm*64 + mt*16)*136 + wn*32 + nt*16,
                                    acc[mt][nt], 136, wmma::mem_row_major);
    __syncthreads();

    int row = tid >> 1;
    int cb  = (tid & 1) * 64;
    const float* sr = stg + row*136 + cb;
    size_t crow  = (size_t)(m0+row)*Ntot + n0 + cb;
    size_t shrow = (size_t)(m0+row)*(2*(size_t)Ntot) + n0 + cb;
    #pragma unroll
    for (int j = 0; j < 64; j += 4) {
        float4 v = *reinterpret_cast<const float4*>(sr + j);
        if (BMODE) {
            float4 b = *reinterpret_cast<const float4*>(bp + bbase + cb + j);
            v.x += b.x; v.y += b.y; v.z += b.z; v.w += b.w;
        }
        if (RELU) {
            v.x = fmaxf(v.x, 0.f); v.y = fmaxf(v.y, 0.f);
            v.z = fmaxf(v.z, 0.f); v.w = fmaxf(v.w, 0.f);
        }
        if (WF32) *reinterpret_cast<float4*>(C + crow + j) = v;
        if (WSPLIT) {
            __nv_bfloat162 h01, l01, h23, l23;
            split2(v.x, v.y, h01, l01);
            split2(v.z, v.w, h23, l23);
            __nv_bfloat16* hp = Csp + shrow + j;
            *reinterpret_cast<__nv_bfloat162*>(hp)     = h01;
            *reinterpret_cast<__nv_bfloat162*>(hp + 2) = h23;
            *reinterpret_cast<__nv_bfloat162*>(hp + Ntot)     = l01;
            *reinterpret_cast<__nv_bfloat162*>(hp + Ntot + 2) = l23;
        }
    }
}

// ---------------- sparse GCN aggregation (+bias +relu) ----------------------
template<bool WF32>
__global__ void __launch_bounds__(256)
agg_csr(const float* __restrict__ xw, const int* __restrict__ rp,
        const int* __restrict__ ci, const float* __restrict__ wv,
        const float* __restrict__ bias, float* __restrict__ outf,
        __nv_bfloat16* __restrict__ sp)
{
    int warp = blockIdx.x*8 + (threadIdx.x >> 5);
    int lane = threadIdx.x & 31;
    int p = warp & 127;
    size_t gbase = (size_t)(warp & ~127) * Dn;

    float4 a0 = make_float4(0.f,0.f,0.f,0.f);
    float4 a1 = make_float4(0.f,0.f,0.f,0.f);
    int s0 = rp[p], s1 = rp[p+1];
    for (int e = s0; e < s1; e++) {
        int src = ci[e]; float w = wv[e];
        const float4* rowp = reinterpret_cast<const float4*>(xw + gbase + (size_t)src*Dn);
        float4 x0 = rowp[lane];
        float4 x1 = rowp[lane+32];
        a0.x = fmaf(w, x0.x, a0.x); a0.y = fmaf(w, x0.y, a0.y);
        a0.z = fmaf(w, x0.z, a0.z); a0.w = fmaf(w, x0.w, a0.w);
        a1.x = fmaf(w, x1.x, a1.x); a1.y = fmaf(w, x1.y, a1.y);
        a1.z = fmaf(w, x1.z, a1.z); a1.w = fmaf(w, x1.w, a1.w);
    }
    int c0 = lane*4;
    float4 b0 = *reinterpret_cast<const float4*>(bias + c0);
    float4 b1 = *reinterpret_cast<const float4*>(bias + c0 + 128);
    a0.x = fmaxf(a0.x + b0.x, 0.f); a0.y = fmaxf(a0.y + b0.y, 0.f);
    a0.z = fmaxf(a0.z + b0.z, 0.f); a0.w = fmaxf(a0.w + b0.w, 0.f);
    a1.x = fmaxf(a1.x + b1.x, 0.f); a1.y = fmaxf(a1.y + b1.y, 0.f);
    a1.z = fmaxf(a1.z + b1.z, 0.f); a1.w = fmaxf(a1.w + b1.w, 0.f);

    if (WF32) {
        float* dst = outf + (size_t)warp*Dn;
        *reinterpret_cast<float4*>(dst + c0)       = a0;
        *reinterpret_cast<float4*>(dst + c0 + 128) = a1;
    }
    __nv_bfloat16* sprow = sp + (size_t)warp*512;
    __nv_bfloat162 h01, l01, h23, l23;
    split2(a0.x, a0.y, h01, l01); split2(a0.z, a0.w, h23, l23);
    *reinterpret_cast<__nv_bfloat162*>(sprow + c0)     = h01;
    *reinterpret_cast<__nv_bfloat162*>(sprow + c0 + 2) = h23;
    *reinterpret_cast<__nv_bfloat162*>(sprow + 256 + c0)     = l01;
    *reinterpret_cast<__nv_bfloat162*>(sprow + 256 + c0 + 2) = l23;
    split2(a1.x, a1.y, h01, l01); split2(a1.z, a1.w, h23, l23);
    *reinterpret_cast<__nv_bfloat162*>(sprow + c0 + 128)     = h01;
    *reinterpret_cast<__nv_bfloat162*>(sprow + c0 + 130)     = h23;
    *reinterpret_cast<__nv_bfloat162*>(sprow + 256 + c0 + 128) = l01;
    *reinterpret_cast<__nv_bfloat162*>(sprow + 256 + c0 + 130) = l23;
}

// ---------------- attention: f32x2-packed, one CTA per (head, graph) -------
__global__ void __launch_bounds__(128)
attn_kernel(const float* __restrict__ qkv, __nv_bfloat16* __restrict__ sp)
{
    int head = blockIdx.x;
    int g    = blockIdx.y;
    int tid  = threadIdx.x;

    __shared__ u64t Ks[Pn][HDn/2];
    __shared__ u64t Vs[Pn][HDn/2];

    size_t base = ((size_t)g*Pn + tid)*768 + head*HDn;
    u64t qr[HDn/2];
    #pragma unroll
    for (int j = 0; j < HDn/4; j++) {
        float4 qv = reinterpret_cast<const float4*>(qkv + base)[j];
        float4 kv = reinterpret_cast<const float4*>(qkv + base + 256)[j];
        float4 vv = reinterpret_cast<const float4*>(qkv + base + 512)[j];
        qr[2*j]   = f2pack(qv.x, qv.y);
        qr[2*j+1] = f2pack(qv.z, qv.w);
        Ks[tid][2*j]   = f2pack(kv.x, kv.y);
        Ks[tid][2*j+1] = f2pack(kv.z, kv.w);
        Vs[tid][2*j]   = f2pack(vv.x, vv.y);
        Vs[tid][2*j+1] = f2pack(vv.z, vv.w);
    }
    __syncthreads();

    const float scale = 0.17677669529663687f;   // 1/sqrt(32)
    float l = 0.f;
    u64t acc[HDn/2];
    #pragma unroll
    for (int d = 0; d < HDn/2; d++) acc[d] = 0ull;

    for (int j = 0; j < Pn; j++) {
        u64t s2 = 0ull;
        #pragma unroll
        for (int d = 0; d < HDn/2; d++) s2 = fma2(qr[d], Ks[j][d], s2);
        float2 sv = f2unpack(s2);
        float e = __expf((sv.x + sv.y)*scale);
        l += e;
        u64t ee = f2pack(e, e);
        #pragma unroll
        for (int d = 0; d < HDn/2; d++) acc[d] = fma2(ee, Vs[j][d], acc[d]);
    }
    float inv = 1.f / l;
    __nv_bfloat16* sprow = sp + ((size_t)g*Pn + tid)*512 + head*HDn;
    #pragma unroll
    for (int d = 0; d < HDn/2; d += 2) {
        float2 p0 = f2unpack(acc[d]);
        float2 p1 = f2unpack(acc[d+1]);
        __nv_bfloat162 h01, l01, h23, l23;
        split2(p0.x*inv, p0.y*inv, h01, l01);
        split2(p1.x*inv, p1.y*inv, h23, l23);
        *reinterpret_cast<__nv_bfloat162*>(sprow + 2*d)     = h01;
        *reinterpret_cast<__nv_bfloat162*>(sprow + 2*d + 2) = h23;
        *reinterpret_cast<__nv_bfloat162*>(sprow + 256 + 2*d)     = l01;
        *reinterpret_cast<__nv_bfloat162*>(sprow + 256 + 2*d + 2) = l23;
    }
}

// ---------------- LayerNorm(x + t)*g + b --------------------------------
template<bool WSPLIT>
__global__ void __launch_bounds__(Dn)
ln_kernel(const float* __restrict__ x, const float* __restrict__ t,
          const float* __restrict__ gam, const float* __restrict__ bet,
          float* __restrict__ out, __nv_bfloat16* __restrict__ sp)
{
    int row = blockIdx.x;
    int f   = threadIdx.x;
    size_t idx = (size_t)row*Dn + f;
    float v = x[idx] + t[idx];

    __shared__ float sh[8];
    int lane = f & 31, w = f >> 5;

    float s = v;
    #pragma unroll
    for (int off = 16; off > 0; off >>= 1) s += __shfl_xor_sync(0xffffffffu, s, off);
    if (lane == 0) sh[w] = s;
    __syncthreads();
    float mean = 0.f;
    #pragma unroll
    for (int i = 0; i < 8; i++) mean += sh[i];
    mean *= (1.f/Dn);

    float d  = v - mean;
    float s2 = d*d;
    #pragma unroll
    for (int off = 16; off > 0; off >>= 1) s2 += __shfl_xor_sync(0xffffffffu, s2, off);
    __syncthreads();
    if (lane == 0) sh[w] = s2;
    __syncthreads();
    float var = 0.f;
    #pragma unroll
    for (int i = 0; i < 8; i++) var += sh[i];
    var *= (1.f/Dn);

    float r = rsqrtf(var + 1e-5f);
    float o = d*r*gam[f] + bet[f];
    out[idx] = o;
    if (WSPLIT) {
        __nv_bfloat16 hb = __float2bfloat16_rn(o);
        __nv_bfloat16 lb = __float2bfloat16_rn(o - __bfloat162float(hb));
        sp[(size_t)row*512 + f]       = hb;
        sp[(size_t)row*512 + 256 + f] = lb;
    }
}

// ---------------------------------------------------------------------------
extern "C" void kernel_launch(void* const* d_in, const int* in_sizes, int n_in,
                              void* d_out, int out_size)
{
    const float* x    = (const float*)d_in[0];
    const int*   ei   = (const int*)  d_in[1];
    const float* c1W  = (const float*)d_in[6];
    const float* c1b  = (const float*)d_in[7];
    const float* c2W  = (const float*)d_in[8];
    const float* c2b  = (const float*)d_in[9];
    const float* WqA  = (const float*)d_in[10];
    const float* bqA  = (const float*)d_in[11];
    const float* WkA  = (const float*)d_in[12];
    const float* bkA  = (const float*)d_in[13];
    const float* WvA  = (const float*)d_in[14];
    const float* bvA  = (const float*)d_in[15];
    const float* WoA  = (const float*)d_in[16];
    const float* boA  = (const float*)d_in[17];
    const float* W1A  = (const float*)d_in[18];
    const float* b1A  = (const float*)d_in[19];
    const float* W2A  = (const float*)d_in[20];
    const float* b2A  = (const float*)d_in[21];
    const float* l1gA = (const float*)d_in[22];
    const float* l1bA = (const float*)d_in[23];
    const float* l2gA = (const float*)d_in[24];
    const float* l2bA = (const float*)d_in[25];
    float* out = (float*)d_out;

    float *h, *tmp, *qkv, *wv;
    __nv_bfloat16 *as1, *as2, *w3;
    int *rp, *ci;
    cudaGetSymbolAddress((void**)&h,    g_h);
    cudaGetSymbolAddress((void**)&tmp,  g_tmp);
    cudaGetSymbolAddress((void**)&qkv,  g_qkv);
    cudaGetSymbolAddress((void**)&as1,  g_as1);
    cudaGetSymbolAddress((void**)&as2,  g_as2);
    cudaGetSymbolAddress((void**)&w3,   g_w3);
    cudaGetSymbolAddress((void**)&rp,   g_rp);
    cudaGetSymbolAddress((void**)&ci,   g_ci);
    cudaGetSymbolAddress((void**)&wv,   g_wv);

    cudaFuncSetAttribute(gemm_tc<0,false,true ,false>, cudaFuncAttributeMaxDynamicSharedMemorySize, GEMM_SMEM);
    cudaFuncSetAttribute(gemm_tc<2,false,true ,false>, cudaFuncAttributeMaxDynamicSharedMemorySize, GEMM_SMEM);
    cudaFuncSetAttribute(gemm_tc<1,false,true ,false>, cudaFuncAttributeMaxDynamicSharedMemorySize, GEMM_SMEM);
    cudaFuncSetAttribute(gemm_tc<1,true ,false,true >, cudaFuncAttributeMaxDynamicSharedMemorySize, GEMM_SMEM);

    // ---- launch 0: graph setup ----
    k_setup<<<1, Pn>>>(ei, rp, ci, wv);

    // ---- launch 1: all weight packs ----
    const long long oC1 = 0, oC2 = W3_CONV;
    const long long oL  = 2*W3_CONV;
    WPack wp;
    {
        int i = 0;
        long long s = 0;
        auto add = [&](const float* src, long long dst, int K, int N) {
            wp.d[i] = {src, dst, K, N};
            wp.start[i] = s;
            s += (long long)K*N;
            i++;
        };
        add(c1W, oC1, Dn, Dn);
        add(c2W, oC2, Dn, Dn);
        for (int l = 0; l < 2; l++) {
            long long b = oL + (long long)l*W3_LAYER;
            add(WqA + (size_t)l*65536,  b,             Dn, Dn);
            add(WkA + (size_t)l*65536,  b + W3_CONV,   Dn, Dn);
            add(WvA + (size_t)l*65536,  b + 2*W3_CONV, Dn, Dn);
            add(WoA + (size_t)l*65536,  b + 3*W3_CONV, Dn, Dn);
            add(W1A + (size_t)l*262144, b + 4*W3_CONV, Dn, DFn);
            add(W2A + (size_t)l*262144, b + 4*W3_CONV + W3_FFN, DFn, Dn);
        }
        wp.start[14] = s;
    }
    k_wprepAll<<<(int)((wp.start[14] + 255)/256), 256>>>(wp);

    // ---- launch 2: input split ----
    k_asplit<<<(Mn*64)/256, 256>>>(x, as1);

    dim3 gD(2, Mn/128);      // N=256 GEMMs, 1024 CTAs
    dim3 gQKV(6, Mn/128);    // N=768 fused QKV, 3072 CTAs
    dim3 gF1(8, Mn/128);     // N=1024 FFN1, 4096 CTAs

    // ---- launch 3 (profiled): GCN conv1 GEMM ----
    gemm_tc<0,false,true,false><<<gD, 256, GEMM_SMEM>>>(as1, 512, w3 + oC1, 768, nullptr, nullptr, nullptr, tmp, nullptr, Dn, Dn);
    agg_csr<false><<<Mn/8, 256>>>(tmp, rp, ci, wv, c1b, nullptr, as1);
    gemm_tc<0,false,true,false><<<gD, 256, GEMM_SMEM>>>(as1, 512, w3 + oC2, 768, nullptr, nullptr, nullptr, tmp, nullptr, Dn, Dn);
    agg_csr<true ><<<Mn/8, 256>>>(tmp, rp, ci, wv, c2b, h, as1);

    for (int l = 0; l < 2; l++) {
        long long b = oL + (long long)l*W3_LAYER;
        const float* bq = bqA + (size_t)l*Dn;
        const float* bk = bkA + (size_t)l*Dn;
        const float* bv = bvA + (size_t)l*Dn;
        const float* bo = boA + (size_t)l*Dn;
        const float* b1 = b1A + (size_t)l*DFn;
        const float* b2 = b2A + (size_t)l*Dn;
        const float* l1g = l1gA + (size_t)l*Dn; const float* l1b = l1bA + (size_t)l*Dn;
        const float* l2g = l2gA + (size_t)l*Dn; const float* l2b = l2bA + (size_t)l*Dn;

        // fused QKV: B rows 0..767 = Wq|Wk|Wv packs (contiguous)
        gemm_tc<2,false,true,false><<<gQKV, 256, GEMM_SMEM>>>(as1, 512, w3 + b, 768, bq, bk, bv, qkv, nullptr, Dn, 768);

        attn_kernel<<<dim3(Hn, Gn), 128>>>(qkv, as1);

        gemm_tc<1,false,true,false><<<gD, 256, GEMM_SMEM>>>(as1, 512, w3 + b + 3*W3_CONV, 768, bo, nullptr, nullptr, tmp, nullptr, Dn, Dn);
        ln_kernel<true><<<Mn, Dn>>>(h, tmp, l1g, l1b, h, as1);

        gemm_tc<1,true,false,true><<<gF1, 256, GEMM_SMEM>>>(as1, 512, w3 + b + 4*W3_CONV, 768, b1, nullptr, nullptr, nullptr, as2, Dn, DFn);
        gemm_tc<1,false,true,false><<<gD, 256, GEMM_SMEM>>>(as2, 2048, w3 + b + 4*W3_CONV + W3_FFN, 3072, b2, nullptr, nullptr, tmp, nullptr, DFn, Dn);

        if (l == 0) ln_kernel<true ><<<Mn, Dn>>>(h, tmp, l2g, l2b, h, as1);
        else        ln_kernel<false><<<Mn, Dn>>>(h, tmp, l2g, l2b, out, nullptr);
    }
}

// round 7
// speedup vs baseline: 1.2486x; 1.1242x over previous
#include <cuda_runtime.h>
#include <cuda_bf16.h>
#include <mma.h>
#include <math.h>
#include <stdint.h>

using namespace nvcuda;

#define Gn 512
#define Pn 128
#define Dn 256
#define En 1024
#define Hn 8
#define HDn 32
#define DFn 1024
#define Mn (Gn*Pn)

typedef unsigned long long u64t;

// ---------------- scratch ----------------
__device__ float g_h[(size_t)Mn*Dn];
__device__ float g_tmp[(size_t)Mn*Dn];
__device__ float g_qkv[(size_t)Mn*3*Dn];
__device__ __nv_bfloat16 g_as1[(size_t)Mn*2*Dn];
__device__ __nv_bfloat16 g_as2[(size_t)Mn*2*DFn];

// packed weights: [N][2K] bf16 = hi | lo
#define W2_CONV   (Dn*2*Dn)                   // 131072
#define W2_FFN    (DFn*2*Dn)                  // 524288 (same size both FFN dirs)
#define W2_LAYER  (4*W2_CONV + 2*W2_FFN)
__device__ __nv_bfloat16 g_w2[2*W2_CONV + 2*W2_LAYER];

__device__ int   g_rp[Pn+1];
__device__ int   g_ci[En+Pn];
__device__ float g_wv[En+Pn];

// ---------------- helpers ----------------
__device__ __forceinline__ uint32_t smem_u32(const void* p) {
    uint32_t a;
    asm("{ .reg .u64 t; cvta.to.shared.u64 t, %1; cvt.u32.u64 %0, t; }" : "=r"(a) : "l"(p));
    return a;
}
__device__ __forceinline__ void cp_async16(uint32_t dst, const void* src) {
    asm volatile("cp.async.cg.shared.global [%0], [%1], 16;" :: "r"(dst), "l"(src) : "memory");
}
__device__ __forceinline__ void cp_commit() {
    asm volatile("cp.async.commit_group;" ::: "memory");
}
template<int N>
__device__ __forceinline__ void cp_wait() {
    asm volatile("cp.async.wait_group %0;" :: "n"(N) : "memory");
}
__device__ __forceinline__ u64t f2pack(float lo, float hi) {
    u64t r; asm("mov.b64 %0, {%1, %2};" : "=l"(r) : "f"(lo), "f"(hi)); return r;
}
__device__ __forceinline__ float2 f2unpack(u64t v) {
    float x, y; asm("mov.b64 {%0, %1}, %2;" : "=f"(x), "=f"(y) : "l"(v));
    return make_float2(x, y);
}
__device__ __forceinline__ u64t fma2(u64t a, u64t b, u64t c) {
    u64t d; asm("fma.rn.f32x2 %0, %1, %2, %3;" : "=l"(d) : "l"(a), "l"(b), "l"(c)); return d;
}
__device__ __forceinline__ void split2(float a, float b, __nv_bfloat162& hi, __nv_bfloat162& lo) {
    hi = __floats2bfloat162_rn(a, b);
    float2 f = __bfloat1622float2(hi);
    lo = __floats2bfloat162_rn(a - f.x, b - f.y);
}

// ---------------- fused graph setup (1 block) ----------------
__global__ void k_setup(const int* __restrict__ ei, int* rp, int* ci, float* wv) {
    __shared__ int   deg[Pn];
    __shared__ float dinv[Pn];
    __shared__ int   srp[Pn+1];
    __shared__ int   cur[Pn];
    int t = threadIdx.x;   // 128
    deg[t] = 1;
    __syncthreads();
    for (int e = t; e < En; e += Pn) atomicAdd(&deg[ei[En + e]], 1);
    __syncthreads();
    dinv[t] = rsqrtf((float)deg[t]);
    __syncthreads();
    if (t == 0) {
        int s = 0;
        for (int i = 0; i < Pn; i++) { srp[i] = s; cur[i] = s; s += deg[i]; }
        srp[Pn] = s;
    }
    __syncthreads();
    for (int e = t; e < En; e += Pn) {
        int s = ei[e], d = ei[En + e];
        int pos = atomicAdd(&cur[d], 1);
        ci[pos] = s; wv[pos] = dinv[s]*dinv[d];
    }
    {   // self loops
        int pos = atomicAdd(&cur[t], 1);
        ci[pos] = t; wv[pos] = dinv[t]*dinv[t];
    }
    rp[t] = srp[t];
    if (t == 0) rp[Pn] = srp[Pn];
}

// ---------------- fused weight pack: W[K,N] fp32 -> [N][2K] hi|lo ----------
struct WD { const float* src; long long dst; int K; int N; };
struct WPack { WD d[14]; long long start[15]; };

__global__ void k_wprepAll(WPack p) {
    long long idx = (long long)blockIdx.x*256 + threadIdx.x;
    if (idx >= p.start[14]) return;
    int r = 0;
    #pragma unroll
    for (int i = 1; i < 14; i++) if (idx >= p.start[i]) r = i;
    long long local = idx - p.start[r];
    const WD d = p.d[r];
    int k = (int)(local / d.N), n = (int)(local - (long long)k*d.N);
    float a = d.src[local];
    __nv_bfloat16 h = __float2bfloat16_rn(a);
    __nv_bfloat16 l = __float2bfloat16_rn(a - __bfloat162float(h));
    __nv_bfloat16* O = g_w2 + d.dst + (size_t)n*2*d.K;
    O[k]       = h;
    O[d.K + k] = l;
}

// ---------------- input split: X[M,256] fp32 -> S[M,512] bf16 ---------------
__global__ void k_asplit(const float* __restrict__ X, __nv_bfloat16* __restrict__ S) {
    int idx = blockIdx.x*blockDim.x + threadIdx.x;
    int row = idx >> 6;
    int g   = (idx & 63) * 4;
    float4 v = reinterpret_cast<const float4*>(X)[idx];
    __nv_bfloat162 h01, l01, h23, l23;
    split2(v.x, v.y, h01, l01);
    split2(v.z, v.w, h23, l23);
    __nv_bfloat16* hp = S + (size_t)row*512 + g;
    *reinterpret_cast<__nv_bfloat162*>(hp)     = h01;
    *reinterpret_cast<__nv_bfloat162*>(hp + 2) = h23;
    *reinterpret_cast<__nv_bfloat162*>(hp + 256)     = l01;
    *reinterpret_cast<__nv_bfloat162*>(hp + 256 + 2) = l23;
}

// ---------------- WMMA GEMM, per-chunk 3-product split ----------------------
// A2: [M][2K] hi|lo ; B2: [N][2K] hi|lo. BM=BN=128, BK=32, 2 stages, 2 CTA/SM.
// Per chunk: load Ahi,Alo,Bhi,Blo once; acc += AhiBhi + AhiBlo + AloBhi.
#define ASTR 40
#define TILE_B 10240             // one 128x32 bf16 tile padded to stride 40
#define STAGE_B (4*TILE_B)       // 40960
#define GEMM_SMEM (2*STAGE_B)    // 81920 >= epilogue 128*136*4 = 69632

template<int BMODE, bool RELU, bool WF32, bool WSPLIT>
__global__ void __launch_bounds__(256, 2)
gemm_tc(const __nv_bfloat16* __restrict__ A2, long long lda,
        const __nv_bfloat16* __restrict__ B2, long long ldb,
        const float* __restrict__ b0, const float* __restrict__ b1p,
        const float* __restrict__ b2p,
        float* __restrict__ C, __nv_bfloat16* __restrict__ Csp,
        int K, int Ntot)
{
    extern __shared__ __align__(128) char dsm[];
    const int tid = threadIdx.x;
    const int wid = tid >> 5;
    const int wm = wid & 1;       // 0..1  (64-row slice)
    const int wn = wid >> 1;      // 0..3  (32-col slice)
    const int m0 = blockIdx.y * 128;
    const int n0 = blockIdx.x * 128;
    uint32_t sbase = smem_u32(dsm);

    const int nc = K >> 5;

    wmma::fragment<wmma::accumulator, 16,16,16, float> acc[4][2];
    #pragma unroll
    for (int i = 0; i < 4; i++)
        #pragma unroll
        for (int j = 0; j < 2; j++) wmma::fill_fragment(acc[i][j], 0.f);

    auto load_chunk = [&](int c, int stage) {
        int k0 = c << 5;
        uint32_t base = sbase + stage*STAGE_B;
        #pragma unroll
        for (int r = 0; r < 2; r++) {
            int id = tid + r*256;
            int row = id >> 2, seg = id & 3;
            const __nv_bfloat16* arow = A2 + (size_t)(m0+row)*lda + seg*8;
            const __nv_bfloat16* brow = B2 + (size_t)(n0+row)*ldb + seg*8;
            uint32_t soff = row*80 + seg*16;
            cp_async16(base + soff,            arow + k0);        // A hi
            cp_async16(base + TILE_B + soff,   arow + K + k0);    // A lo
            cp_async16(base + 2*TILE_B + soff, brow + k0);        // B hi
            cp_async16(base + 3*TILE_B + soff, brow + K + k0);    // B lo
        }
        cp_commit();
    };

    load_chunk(0, 0);

    for (int c = 0; c < nc; c++) {
        const int stage = c & 1;
        cp_wait<0>();
        __syncthreads();
        if (c + 1 < nc) load_chunk(c+1, stage^1);

        const __nv_bfloat16* Ah = reinterpret_cast<const __nv_bfloat16*>(dsm + stage*STAGE_B);
        const __nv_bfloat16* Al = Ah + 5120;    // TILE_B bytes = 5120 elems
        const __nv_bfloat16* Bh = Ah + 10240;
        const __nv_bfloat16* Bl = Ah + 15360;

        #pragma unroll
        for (int ks = 0; ks < 2; ks++) {
            wmma::fragment<wmma::matrix_b, 16,16,16, __nv_bfloat16, wmma::col_major> bh[2], bl[2];
            #pragma unroll
            for (int nt = 0; nt < 2; nt++) {
                wmma::load_matrix_sync(bh[nt], Bh + (wn*32 + nt*16)*ASTR + ks*16, ASTR);
                wmma::load_matrix_sync(bl[nt], Bl + (wn*32 + nt*16)*ASTR + ks*16, ASTR);
            }
            // hi*hi and hi*lo, A in pairs to bound register pressure
            #pragma unroll
            for (int half = 0; half < 2; half++) {
                wmma::fragment<wmma::matrix_a, 16,16,16, __nv_bfloat16, wmma::row_major> a2[2];
                #pragma unroll
                for (int i = 0; i < 2; i++)
                    wmma::load_matrix_sync(a2[i], Ah + (wm*64 + half*32 + i*16)*ASTR + ks*16, ASTR);
                #pragma unroll
                for (int i = 0; i < 2; i++)
                    #pragma unroll
                    for (int nt = 0; nt < 2; nt++) {
                        wmma::mma_sync(acc[half*2+i][nt], a2[i], bh[nt], acc[half*2+i][nt]);
                        wmma::mma_sync(acc[half*2+i][nt], a2[i], bl[nt], acc[half*2+i][nt]);
                    }
            }
            // lo*hi
            #pragma unroll
            for (int half = 0; half < 2; half++) {
                wmma::fragment<wmma::matrix_a, 16,16,16, __nv_bfloat16, wmma::row_major> a2[2];
                #pragma unroll
                for (int i = 0; i < 2; i++)
                    wmma::load_matrix_sync(a2[i], Al + (wm*64 + half*32 + i*16)*ASTR + ks*16, ASTR);
                #pragma unroll
                for (int i = 0; i < 2; i++)
                    #pragma unroll
                    for (int nt = 0; nt < 2; nt++)
                        wmma::mma_sync(acc[half*2+i][nt], a2[i], bh[nt], acc[half*2+i][nt]);
            }
        }
    }
    __syncthreads();

    // bias pointer
    const float* bp = nullptr;
    int bbase = 0;
    if (BMODE == 1) { bp = b0; bbase = n0; }
    if (BMODE == 2) {
        int sel = blockIdx.x >> 1;
        bp = (sel == 0) ? b0 : ((sel == 1) ? b1p : b2p);
        bbase = (blockIdx.x & 1) * 128;
    }

    // epilogue: smem-staged, one pass
    float* stg = reinterpret_cast<float*>(dsm);
    #pragma unroll
    for (int mt = 0; mt < 4; mt++)
        #pragma unroll
        for (int nt = 0; nt < 2; nt++)
            wmma::store_matrix_sync(stg + (wm*64 + mt*16)*136 + wn*32 + nt*16,
                                    acc[mt][nt], 136, wmma::mem_row_major);
    __syncthreads();

    int row = tid >> 1;
    int cb  = (tid & 1) * 64;
    const float* sr = stg + row*136 + cb;
    size_t crow  = (size_t)(m0+row)*Ntot + n0 + cb;
    size_t shrow = (size_t)(m0+row)*(2*(size_t)Ntot) + n0 + cb;
    #pragma unroll
    for (int j = 0; j < 64; j += 4) {
        float4 v = *reinterpret_cast<const float4*>(sr + j);
        if (BMODE) {
            float4 b = *reinterpret_cast<const float4*>(bp + bbase + cb + j);
            v.x += b.x; v.y += b.y; v.z += b.z; v.w += b.w;
        }
        if (RELU) {
            v.x = fmaxf(v.x, 0.f); v.y = fmaxf(v.y, 0.f);
            v.z = fmaxf(v.z, 0.f); v.w = fmaxf(v.w, 0.f);
        }
        if (WF32) *reinterpret_cast<float4*>(C + crow + j) = v;
        if (WSPLIT) {
            __nv_bfloat162 h01, l01, h23, l23;
            split2(v.x, v.y, h01, l01);
            split2(v.z, v.w, h23, l23);
            __nv_bfloat16* hp = Csp + shrow + j;
            *reinterpret_cast<__nv_bfloat162*>(hp)     = h01;
            *reinterpret_cast<__nv_bfloat162*>(hp + 2) = h23;
            *reinterpret_cast<__nv_bfloat162*>(hp + Ntot)     = l01;
            *reinterpret_cast<__nv_bfloat162*>(hp + Ntot + 2) = l23;
        }
    }
}

// ---------------- sparse GCN aggregation (+bias +relu) ----------------------
template<bool WF32>
__global__ void __launch_bounds__(256)
agg_csr(const float* __restrict__ xw, const int* __restrict__ rp,
        const int* __restrict__ ci, const float* __restrict__ wv,
        const float* __restrict__ bias, float* __restrict__ outf,
        __nv_bfloat16* __restrict__ sp)
{
    int warp = blockIdx.x*8 + (threadIdx.x >> 5);
    int lane = threadIdx.x & 31;
    int p = warp & 127;
    size_t gbase = (size_t)(warp & ~127) * Dn;

    float4 a0 = make_float4(0.f,0.f,0.f,0.f);
    float4 a1 = make_float4(0.f,0.f,0.f,0.f);
    int s0 = rp[p], s1 = rp[p+1];
    for (int e = s0; e < s1; e++) {
        int src = ci[e]; float w = wv[e];
        const float4* rowp = reinterpret_cast<const float4*>(xw + gbase + (size_t)src*Dn);
        float4 x0 = rowp[lane];
        float4 x1 = rowp[lane+32];
        a0.x = fmaf(w, x0.x, a0.x); a0.y = fmaf(w, x0.y, a0.y);
        a0.z = fmaf(w, x0.z, a0.z); a0.w = fmaf(w, x0.w, a0.w);
        a1.x = fmaf(w, x1.x, a1.x); a1.y = fmaf(w, x1.y, a1.y);
        a1.z = fmaf(w, x1.z, a1.z); a1.w = fmaf(w, x1.w, a1.w);
    }
    int c0 = lane*4;
    float4 b0 = *reinterpret_cast<const float4*>(bias + c0);
    float4 b1 = *reinterpret_cast<const float4*>(bias + c0 + 128);
    a0.x = fmaxf(a0.x + b0.x, 0.f); a0.y = fmaxf(a0.y + b0.y, 0.f);
    a0.z = fmaxf(a0.z + b0.z, 0.f); a0.w = fmaxf(a0.w + b0.w, 0.f);
    a1.x = fmaxf(a1.x + b1.x, 0.f); a1.y = fmaxf(a1.y + b1.y, 0.f);
    a1.z = fmaxf(a1.z + b1.z, 0.f); a1.w = fmaxf(a1.w + b1.w, 0.f);

    if (WF32) {
        float* dst = outf + (size_t)warp*Dn;
        *reinterpret_cast<float4*>(dst + c0)       = a0;
        *reinterpret_cast<float4*>(dst + c0 + 128) = a1;
    }
    __nv_bfloat16* sprow = sp + (size_t)warp*512;
    __nv_bfloat162 h01, l01, h23, l23;
    split2(a0.x, a0.y, h01, l01); split2(a0.z, a0.w, h23, l23);
    *reinterpret_cast<__nv_bfloat162*>(sprow + c0)     = h01;
    *reinterpret_cast<__nv_bfloat162*>(sprow + c0 + 2) = h23;
    *reinterpret_cast<__nv_bfloat162*>(sprow + 256 + c0)     = l01;
    *reinterpret_cast<__nv_bfloat162*>(sprow + 256 + c0 + 2) = l23;
    split2(a1.x, a1.y, h01, l01); split2(a1.z, a1.w, h23, l23);
    *reinterpret_cast<__nv_bfloat162*>(sprow + c0 + 128)     = h01;
    *reinterpret_cast<__nv_bfloat162*>(sprow + c0 + 130)     = h23;
    *reinterpret_cast<__nv_bfloat162*>(sprow + 256 + c0 + 128) = l01;
    *reinterpret_cast<__nv_bfloat162*>(sprow + 256 + c0 + 130) = l23;
}

// ---------------- attention: f32x2-packed, one CTA per (head, graph) -------
__global__ void __launch_bounds__(128)
attn_kernel(const float* __restrict__ qkv, __nv_bfloat16* __restrict__ sp)
{
    int head = blockIdx.x;
    int g    = blockIdx.y;
    int tid  = threadIdx.x;

    __shared__ u64t Ks[Pn][HDn/2];
    __shared__ u64t Vs[Pn][HDn/2];

    size_t base = ((size_t)g*Pn + tid)*768 + head*HDn;
    u64t qr[HDn/2];
    #pragma unroll
    for (int j = 0; j < HDn/4; j++) {
        float4 qv = reinterpret_cast<const float4*>(qkv + base)[j];
        float4 kv = reinterpret_cast<const float4*>(qkv + base + 256)[j];
        float4 vv = reinterpret_cast<const float4*>(qkv + base + 512)[j];
        qr[2*j]   = f2pack(qv.x, qv.y);
        qr[2*j+1] = f2pack(qv.z, qv.w);
        Ks[tid][2*j]   = f2pack(kv.x, kv.y);
        Ks[tid][2*j+1] = f2pack(kv.z, kv.w);
        Vs[tid][2*j]   = f2pack(vv.x, vv.y);
        Vs[tid][2*j+1] = f2pack(vv.z, vv.w);
    }
    __syncthreads();

    const float scale = 0.17677669529663687f;   // 1/sqrt(32)
    float l = 0.f;
    u64t acc[HDn/2];
    #pragma unroll
    for (int d = 0; d < HDn/2; d++) acc[d] = 0ull;

    for (int j = 0; j < Pn; j++) {
        u64t s2 = 0ull;
        #pragma unroll
        for (int d = 0; d < HDn/2; d++) s2 = fma2(qr[d], Ks[j][d], s2);
        float2 sv = f2unpack(s2);
        float e = __expf((sv.x + sv.y)*scale);
        l += e;
        u64t ee = f2pack(e, e);
        #pragma unroll
        for (int d = 0; d < HDn/2; d++) acc[d] = fma2(ee, Vs[j][d], acc[d]);
    }
    float inv = 1.f / l;
    __nv_bfloat16* sprow = sp + ((size_t)g*Pn + tid)*512 + head*HDn;
    #pragma unroll
    for (int d = 0; d < HDn/2; d += 2) {
        float2 p0 = f2unpack(acc[d]);
        float2 p1 = f2unpack(acc[d+1]);
        __nv_bfloat162 h01, l01, h23, l23;
        split2(p0.x*inv, p0.y*inv, h01, l01);
        split2(p1.x*inv, p1.y*inv, h23, l23);
        *reinterpret_cast<__nv_bfloat162*>(sprow + 2*d)     = h01;
        *reinterpret_cast<__nv_bfloat162*>(sprow + 2*d + 2) = h23;
        *reinterpret_cast<__nv_bfloat162*>(sprow + 256 + 2*d)     = l01;
        *reinterpret_cast<__nv_bfloat162*>(sprow + 256 + 2*d + 2) = l23;
    }
}

// ---------------- LayerNorm(x + t)*g + b --------------------------------
template<bool WSPLIT>
__global__ void __launch_bounds__(Dn)
ln_kernel(const float* __restrict__ x, const float* __restrict__ t,
          const float* __restrict__ gam, const float* __restrict__ bet,
          float* __restrict__ out, __nv_bfloat16* __restrict__ sp)
{
    int row = blockIdx.x;
    int f   = threadIdx.x;
    size_t idx = (size_t)row*Dn + f;
    float v = x[idx] + t[idx];

    __shared__ float sh[8];
    int lane = f & 31, w = f >> 5;

    float s = v;
    #pragma unroll
    for (int off = 16; off > 0; off >>= 1) s += __shfl_xor_sync(0xffffffffu, s, off);
    if (lane == 0) sh[w] = s;
    __syncthreads();
    float mean = 0.f;
    #pragma unroll
    for (int i = 0; i < 8; i++) mean += sh[i];
    mean *= (1.f/Dn);

    float d  = v - mean;
    float s2 = d*d;
    #pragma unroll
    for (int off = 16; off > 0; off >>= 1) s2 += __shfl_xor_sync(0xffffffffu, s2, off);
    __syncthreads();
    if (lane == 0) sh[w] = s2;
    __syncthreads();
    float var = 0.f;
    #pragma unroll
    for (int i = 0; i < 8; i++) var += sh[i];
    var *= (1.f/Dn);

    float r = rsqrtf(var + 1e-5f);
    float o = d*r*gam[f] + bet[f];
    out[idx] = o;
    if (WSPLIT) {
        __nv_bfloat16 hb = __float2bfloat16_rn(o);
        __nv_bfloat16 lb = __float2bfloat16_rn(o - __bfloat162float(hb));
        sp[(size_t)row*512 + f]       = hb;
        sp[(size_t)row*512 + 256 + f] = lb;
    }
}

// ---------------------------------------------------------------------------
extern "C" void kernel_launch(void* const* d_in, const int* in_sizes, int n_in,
                              void* d_out, int out_size)
{
    const float* x    = (const float*)d_in[0];
    const int*   ei   = (const int*)  d_in[1];
    const float* c1W  = (const float*)d_in[6];
    const float* c1b  = (const float*)d_in[7];
    const float* c2W  = (const float*)d_in[8];
    const float* c2b  = (const float*)d_in[9];
    const float* WqA  = (const float*)d_in[10];
    const float* bqA  = (const float*)d_in[11];
    const float* WkA  = (const float*)d_in[12];
    const float* bkA  = (const float*)d_in[13];
    const float* WvA  = (const float*)d_in[14];
    const float* bvA  = (const float*)d_in[15];
    const float* WoA  = (const float*)d_in[16];
    const float* boA  = (const float*)d_in[17];
    const float* W1A  = (const float*)d_in[18];
    const float* b1A  = (const float*)d_in[19];
    const float* W2A  = (const float*)d_in[20];
    const float* b2A  = (const float*)d_in[21];
    const float* l1gA = (const float*)d_in[22];
    const float* l1bA = (const float*)d_in[23];
    const float* l2gA = (const float*)d_in[24];
    const float* l2bA = (const float*)d_in[25];
    float* out = (float*)d_out;

    float *h, *tmp, *qkv, *wv;
    __nv_bfloat16 *as1, *as2, *w2;
    int *rp, *ci;
    cudaGetSymbolAddress((void**)&h,    g_h);
    cudaGetSymbolAddress((void**)&tmp,  g_tmp);
    cudaGetSymbolAddress((void**)&qkv,  g_qkv);
    cudaGetSymbolAddress((void**)&as1,  g_as1);
    cudaGetSymbolAddress((void**)&as2,  g_as2);
    cudaGetSymbolAddress((void**)&w2,   g_w2);
    cudaGetSymbolAddress((void**)&rp,   g_rp);
    cudaGetSymbolAddress((void**)&ci,   g_ci);
    cudaGetSymbolAddress((void**)&wv,   g_wv);

    cudaFuncSetAttribute(gemm_tc<0,false,true ,false>, cudaFuncAttributeMaxDynamicSharedMemorySize, GEMM_SMEM);
    cudaFuncSetAttribute(gemm_tc<2,false,true ,false>, cudaFuncAttributeMaxDynamicSharedMemorySize, GEMM_SMEM);
    cudaFuncSetAttribute(gemm_tc<1,false,true ,false>, cudaFuncAttributeMaxDynamicSharedMemorySize, GEMM_SMEM);
    cudaFuncSetAttribute(gemm_tc<1,true ,false,true >, cudaFuncAttributeMaxDynamicSharedMemorySize, GEMM_SMEM);

    // ---- launch 0: graph setup ----
    k_setup<<<1, Pn>>>(ei, rp, ci, wv);

    // ---- launch 1: all weight packs ([N][2K] hi|lo) ----
    const long long oC1 = 0, oC2 = W2_CONV;
    const long long oL  = 2*W2_CONV;
    WPack wp;
    {
        int i = 0;
        long long s = 0;
        auto add = [&](const float* src, long long dst, int K, int N) {
            wp.d[i] = {src, dst, K, N};
            wp.start[i] = s;
            s += (long long)K*N;
            i++;
        };
        add(c1W, oC1, Dn, Dn);
        add(c2W, oC2, Dn, Dn);
        for (int l = 0; l < 2; l++) {
            long long b = oL + (long long)l*W2_LAYER;
            add(WqA + (size_t)l*65536,  b,             Dn, Dn);
            add(WkA + (size_t)l*65536,  b + W2_CONV,   Dn, Dn);
            add(WvA + (size_t)l*65536,  b + 2*W2_CONV, Dn, Dn);
            add(WoA + (size_t)l*65536,  b + 3*W2_CONV, Dn, Dn);
            add(W1A + (size_t)l*262144, b + 4*W2_CONV, Dn, DFn);
            add(W2A + (size_t)l*262144, b + 4*W2_CONV + W2_FFN, DFn, Dn);
        }
        wp.start[14] = s;
    }
    k_wprepAll<<<(int)((wp.start[14] + 255)/256), 256>>>(wp);

    // ---- launch 2: input split ----
    k_asplit<<<(Mn*64)/256, 256>>>(x, as1);

    dim3 gD(2, Mn/128);      // N=256 GEMMs, 1024 CTAs
    dim3 gQKV(6, Mn/128);    // N=768 fused QKV
    dim3 gF1(8, Mn/128);     // N=1024 FFN1

    // ---- launch 3 (profiled): GCN conv1 GEMM ----
    gemm_tc<0,false,true,false><<<gD, 256, GEMM_SMEM>>>(as1, 512, w2 + oC1, 512, nullptr, nullptr, nullptr, tmp, nullptr, Dn, Dn);
    agg_csr<false><<<Mn/8, 256>>>(tmp, rp, ci, wv, c1b, nullptr, as1);
    gemm_tc<0,false,true,false><<<gD, 256, GEMM_SMEM>>>(as1, 512, w2 + oC2, 512, nullptr, nullptr, nullptr, tmp, nullptr, Dn, Dn);
    agg_csr<true ><<<Mn/8, 256>>>(tmp, rp, ci, wv, c2b, h, as1);

    for (int l = 0; l < 2; l++) {
        long long b = oL + (long long)l*W2_LAYER;
        const float* bq = bqA + (size_t)l*Dn;
        const float* bk = bkA + (size_t)l*Dn;
        const float* bv = bvA + (size_t)l*Dn;
        const float* bo = boA + (size_t)l*Dn;
        const float* b1 = b1A + (size_t)l*DFn;
        const float* b2 = b2A + (size_t)l*Dn;
        const float* l1g = l1gA + (size_t)l*Dn; const float* l1b = l1bA + (size_t)l*Dn;
        const float* l2g = l2gA + (size_t)l*Dn; const float* l2b = l2bA + (size_t)l*Dn;

        // fused QKV: B rows 0..767 = Wq|Wk|Wv packs (contiguous, all [.][512])
        gemm_tc<2,false,true,false><<<gQKV, 256, GEMM_SMEM>>>(as1, 512, w2 + b, 512, bq, bk, bv, qkv, nullptr, Dn, 768);

        attn_kernel<<<dim3(Hn, Gn), 128>>>(qkv, as1);

        gemm_tc<1,false,true,false><<<gD, 256, GEMM_SMEM>>>(as1, 512, w2 + b + 3*W2_CONV, 512, bo, nullptr, nullptr, tmp, nullptr, Dn, Dn);
        ln_kernel<true><<<Mn, Dn>>>(h, tmp, l1g, l1b, h, as1);

        gemm_tc<1,true,false,true><<<gF1, 256, GEMM_SMEM>>>(as1, 512, w2 + b + 4*W2_CONV, 512, b1, nullptr, nullptr, nullptr, as2, Dn, DFn);
        gemm_tc<1,false,true,false><<<gD, 256, GEMM_SMEM>>>(as2, 2048, w2 + b + 4*W2_CONV + W2_FFN, 2048, b2, nullptr, nullptr, tmp, nullptr, DFn, Dn);

        if (l == 0) ln_kernel<true ><<<Mn, Dn>>>(h, tmp, l2g, l2b, h, as1);
        else        ln_kernel<false><<<Mn, Dn>>>(h, tmp, l2g, l2b, out, nullptr);
    }
}